// round 7
// baseline (speedup 1.0000x reference)
#include <cuda_runtime.h>
#include <cuda_bf16.h>

// CSR multi-head SpMM: out[n,h,d] = sum_{e in row n} ew[e,h] * nf[col[e],h,d]
// N=50000, E=800000, H=8, D=8 -> 64 floats per row.
//
// Warp per row (R1 structure). R5/R6: stage the row's column indices in SMEM.
// One coalesced LDG+STS per 32 edges (off the critical path); the inner loop
// reads indices via LDS broadcast (29 cyc) instead of a dependent L2 LDG
// (~234 cyc). Per-batch exposed latency: ~470 -> ~263 cycles.
// Lane L owns output floats 2L,2L+1 (float2), head h = L>>2; feature gather
// is a 256B coalesced warp read (node_feat = 12.8MB, L2-resident).

#define H 8
#define D 8
#define ROW_ELEMS (H * D)
#define WARPS_PER_BLOCK 8

__global__ __launch_bounds__(256) void spmm_csr_kernel(
    const int* __restrict__ row_ptr,
    const int* __restrict__ col_idx,
    const float* __restrict__ edge_weight,   // [E, 8]
    const float* __restrict__ node_feat,     // [N, 64]
    float* __restrict__ out,                 // [N, 64]
    int n_nodes)
{
    __shared__ int scol_all[WARPS_PER_BLOCK][32];

    int wip  = threadIdx.x >> 5;                       // warp in block
    int row  = blockIdx.x * WARPS_PER_BLOCK + wip;     // warp per row
    int lane = threadIdx.x & 31;
    if (row >= n_nodes) return;

    int* scol = scol_all[wip];

    int start = __ldg(&row_ptr[row]);
    int end   = __ldg(&row_ptr[row + 1]);

    int h = lane >> 2;                 // head index for this lane's float2
    float accx = 0.0f, accy = 0.0f;

    for (int base = start; base < end; base += 32) {
        // coalesced stage of up to 32 indices (clamped load, masked store ok)
        int e = base + lane;
        int c_stage = __ldg(&col_idx[(e < end) ? e : (end - 1)]);
        scol[lane] = c_stage;
        __syncwarp();

        int nb = end - base; if (nb > 32) nb = 32;          // warp-uniform

        #pragma unroll 4
        for (int j = 0; j < nb; ++j) {
            int c   = scol[j];                              // LDS broadcast
            float w = __ldg(&edge_weight[(size_t)(base + j) * H + h]);
            float2 f = *reinterpret_cast<const float2*>(
                node_feat + (size_t)c * ROW_ELEMS + lane * 2);
            accx = fmaf(w, f.x, accx);
            accy = fmaf(w, f.y, accy);
        }
        __syncwarp();                                       // before restage
    }

    float2 r; r.x = accx; r.y = accy;
    *reinterpret_cast<float2*>(out + (size_t)row * ROW_ELEMS + lane * 2) = r;
}

extern "C" void kernel_launch(void* const* d_in, const int* in_sizes, int n_in,
                              void* d_out, int out_size)
{
    const int*   row_ptr     = (const int*)d_in[0];
    const int*   col_idx     = (const int*)d_in[1];
    const float* edge_weight = (const float*)d_in[2];
    const float* node_feat   = (const float*)d_in[3];
    float*       out         = (float*)d_out;

    int n_nodes = in_sizes[0] - 1;          // row_ptr has N+1 entries

    const int threads = 32 * WARPS_PER_BLOCK;   // 256
    int blocks = (n_nodes + WARPS_PER_BLOCK - 1) / WARPS_PER_BLOCK;
    spmm_csr_kernel<<<blocks, threads>>>(row_ptr, col_idx, edge_weight,
                                         node_feat, out, n_nodes);
}

// round 9
// speedup vs baseline: 1.0945x; 1.0945x over previous
#include <cuda_runtime.h>
#include <cuda_bf16.h>

// CSR multi-head SpMM: out[n,h,d] = sum_{e in row n} ew[e,h] * nf[col[e],h,d]
// N=50000, E=800000, H=8, D=8 -> 64 floats per row.
//
// One warp per destination row (R1 body, best known: 32.8us).
// R7/R8: 64-thread blocks (2 warps) instead of 256. Row lengths are ~Exp(16)
// with a heavy tail; a block retires at max(row lengths of its warps).
// max-of-8 inflates residency ~2.7x (measured: achieved occ 55%, issue 30%,
// nothing else saturated). max-of-2 is ~1.4x; the SM backfills freed CTA
// slots with fresh rows. 32 CTAs/SM x 64 thr = 2048 thr = full occupancy.
//
// Lane L owns output floats 2L,2L+1 (float2), head h = L>>2; feature gather
// is one coalesced 256B warp read (node_feat 12.8MB -> L2-resident).

#define H 8
#define D 8
#define ROW_ELEMS (H * D)
#define THREADS 64

__global__ __launch_bounds__(THREADS) void spmm_csr_kernel(
    const int* __restrict__ row_ptr,
    const int* __restrict__ col_idx,
    const float* __restrict__ edge_weight,   // [E, 8]
    const float* __restrict__ node_feat,     // [N, 64]
    float* __restrict__ out,                 // [N, 64]
    int n_nodes)
{
    int warp = (blockIdx.x * THREADS + threadIdx.x) >> 5;
    int lane = threadIdx.x & 31;
    if (warp >= n_nodes) return;

    int start = __ldg(&row_ptr[warp]);
    int end   = __ldg(&row_ptr[warp + 1]);

    int h = lane >> 2;                 // head index for this lane's float2
    float accx = 0.0f, accy = 0.0f;

    #pragma unroll 4
    for (int e = start; e < end; ++e) {
        int c   = __ldg(&col_idx[e]);
        float w = __ldg(&edge_weight[(size_t)e * H + h]);
        float2 f = *reinterpret_cast<const float2*>(
            node_feat + (size_t)c * ROW_ELEMS + lane * 2);
        accx = fmaf(w, f.x, accx);
        accy = fmaf(w, f.y, accy);
    }

    float2 r; r.x = accx; r.y = accy;
    *reinterpret_cast<float2*>(out + (size_t)warp * ROW_ELEMS + lane * 2) = r;
}

extern "C" void kernel_launch(void* const* d_in, const int* in_sizes, int n_in,
                              void* d_out, int out_size)
{
    const int*   row_ptr     = (const int*)d_in[0];
    const int*   col_idx     = (const int*)d_in[1];
    const float* edge_weight = (const float*)d_in[2];
    const float* node_feat   = (const float*)d_in[3];
    float*       out         = (float*)d_out;

    int n_nodes = in_sizes[0] - 1;          // row_ptr has N+1 entries

    int warps  = n_nodes;                    // warp per row
    int blocks = (warps * 32 + THREADS - 1) / THREADS;
    spmm_csr_kernel<<<blocks, THREADS>>>(row_ptr, col_idx, edge_weight,
                                         node_feat, out, n_nodes);
}